// round 8
// baseline (speedup 1.0000x reference)
#include <cuda_runtime.h>
#include <cuda_fp16.h>
#include <cstdint>
#include <math.h>

// ---------------------------------------------------------------------------
// Problem constants
// ---------------------------------------------------------------------------
#define C_TOT   2048
#define HW2     196
#define O_REAL  48
#define MAXB    64
#define M_TILE  32
#define MTILES  392            // 12544 / 32
#define KC      128            // k per smem chunk
#define NCH     (C_TOT / KC)   // 16 chunks
#define NSTEP   (C_TOT / 32)   // 64 k32 steps

// W fp16 image: per chunk (16), 48 rows x 68 words (64 data + 4 pad).
// Row word layout: k16 step s (8 per chunk) x 8 words:
//   word s*8 + 2c + half : fp16x2( k = 16s + 8*half + 2c, +1 )
#define ROWW    68
#define CHUNKW  (48 * ROWW)            // 3264 words
#define CHUNK_BYTES (CHUNKW * 4)       // 13056
#define CP_UNITS (CHUNK_BYTES / 16)    // 816

// Scratch
__device__ uint32_t g_wimg[(size_t)NCH * CHUNKW];          // 209 KB
__device__ float    g_csum[(size_t)MAXB * HW2 * 8];        // [m][8 classes]
__device__ float    g_t2[(size_t)MAXB * HW2 * 8];          // [m][8]
__device__ float    g_t1s[(size_t)MAXB * 8];               // atomicAdd acc
__device__ unsigned g_gmp_u[(size_t)MAXB * 32];            // atomicMax acc

// ---------------------------------------------------------------------------
// helpers
// ---------------------------------------------------------------------------
__device__ __forceinline__ void hmma16816(float* c, const uint32_t* a,
                                          uint32_t b0, uint32_t b1) {
    asm volatile(
        "mma.sync.aligned.m16n8k16.row.col.f32.f16.f16.f32 "
        "{%0,%1,%2,%3}, {%4,%5,%6,%7}, {%8,%9}, {%0,%1,%2,%3};"
        : "+f"(c[0]), "+f"(c[1]), "+f"(c[2]), "+f"(c[3])
        : "r"(a[0]), "r"(a[1]), "r"(a[2]), "r"(a[3]), "r"(b0), "r"(b1));
}
__device__ __forceinline__ uint32_t h2pack(float e, float o) {
    uint32_t r;
    asm("cvt.rn.f16x2.f32 %0, %1, %2;" : "=r"(r) : "f"(o), "f"(e));
    return r;
}
__device__ __forceinline__ uint32_t smem_u32addr(const void* p) {
    uint32_t a;
    asm("{ .reg .u64 t; cvta.to.shared.u64 t, %1; cvt.u32.u64 %0, t; }" : "=r"(a) : "l"(p));
    return a;
}
__device__ __forceinline__ void cp_async16(uint32_t saddr, const void* gaddr) {
    asm volatile("cp.async.cg.shared.global [%0], [%1], 16;" :: "r"(saddr), "l"(gaddr));
}
// order-preserving float<->uint for atomicMax
__device__ __forceinline__ unsigned fenc(float f) {
    unsigned u = __float_as_uint(f);
    return (u & 0x80000000u) ? ~u : (u | 0x80000000u);
}
__device__ __forceinline__ float fdec(unsigned u) {
    return __uint_as_float((u & 0x80000000u) ? (u & 0x7FFFFFFFu) : ~u);
}

// ---------------------------------------------------------------------------
// Prep: W -> fp16 image (4 words per thread) + zero accumulators.
// Task q < 12288: ci = q/768, n = (q%768)/16, qd = q%16.
//   s = qd>>1, base_k = 16s + 4*(qd&1); words qd*4..+3 =
//   { h2(W[bk],W[bk+1]), h2(W[bk+8],W[bk+9]), h2(W[bk+2],W[bk+3]), h2(W[bk+10],W[bk+11]) }
// ---------------------------------------------------------------------------
__global__ void __launch_bounds__(256) wsl_prep_kernel(
    const float* __restrict__ down_w,
    const float* __restrict__ fc_w)
{
    int q = blockIdx.x * 256 + threadIdx.x;

    // zero accumulators (re-done every launch; graph-replay safe)
    if (q < MAXB * 32) g_gmp_u[q] = 0u;
    if (q < MAXB * 8)  g_t1s[q] = 0.f;

    if (q >= NCH * 48 * 16) return;
    int ci  = q / 768;
    int rem = q - ci * 768;
    int n   = rem >> 4;
    int qd  = rem & 15;
    int s   = qd >> 1;
    int bk  = s * 16 + 4 * (qd & 1);

    const float* wr;
    if (n < 32)      wr = down_w + (size_t)n * C_TOT;
    else if (n < 40) wr = fc_w + (size_t)(n - 32) * (2 * C_TOT);
    else             wr = fc_w + (size_t)(n - 40) * (2 * C_TOT) + C_TOT;

    const float* src = wr + ci * KC + bk;
    float4 f0 = *reinterpret_cast<const float4*>(src);
    float4 f1 = *reinterpret_cast<const float4*>(src + 8);

    uint4 v;
    v.x = h2pack(f0.x, f0.y);
    v.y = h2pack(f1.x, f1.y);
    v.z = h2pack(f0.z, f0.w);
    v.w = h2pack(f1.z, f1.w);
    *reinterpret_cast<uint4*>(g_wimg + (size_t)ci * CHUNKW + n * ROWW + qd * 4) = v;
}

// ---------------------------------------------------------------------------
// Kernel A: fp16 GEMM over full K=2048, fused WSL epilogue.
// Grid 392, 128 threads. Warp w: m rows [(w>>1)*16, +16), n-half (w&1)*24.
// ---------------------------------------------------------------------------
#define XST 49   // epilogue smem row stride (49 mod 32 = 17, conflict-free)

__global__ void __launch_bounds__(128) wsl_mma_kernel(
    const float* __restrict__ x,
    const float* __restrict__ down_b)
{
    __shared__ __align__(16) uint32_t smem[2 * CHUNKW];   // 26.1 KB
    const uint32_t sbase = smem_u32addr(smem);

    const int tid  = threadIdx.x;
    const int wid  = tid >> 5;
    const int lane = tid & 31;
    const int g    = lane >> 2;
    const int c    = lane & 3;
    const int mw   = (wid >> 1) * 16;
    const int nh   = wid & 1;          // n-half: tiles t = nh*3 + {0,1,2}
    const int m_base = blockIdx.x * M_TILE;

    const int m0 = m_base + mw + g;
    const int m1 = m0 + 8;
    const int b0r = m0 / HW2, hw0 = m0 - b0r * HW2;
    const int b1r = m1 / HW2, hw1 = m1 - b1r * HW2;
    const float* pA0 = x + ((size_t)b0r * C_TOT) * HW2 + hw0;
    const float* pA1 = x + ((size_t)b1r * C_TOT) * HW2 + hw1;

    float acc[3][4];
#pragma unroll
    for (int t = 0; t < 3; t++)
#pragma unroll
        for (int j = 0; j < 4; j++) acc[t][j] = 0.f;

    float r0[2][8], r1[2][8];

    auto ldgA = [&](int sg, int p) {
        const int kb = sg * 32 + 2 * c;
#pragma unroll
        for (int j = 0; j < 2; j++) {
            const size_t k = (size_t)(kb + 16 * j);
            r0[p][4 * j]     = __ldg(pA0 + k * HW2);
            r0[p][4 * j + 1] = __ldg(pA0 + (k + 1) * HW2);
            r0[p][4 * j + 2] = __ldg(pA0 + (k + 8) * HW2);
            r0[p][4 * j + 3] = __ldg(pA0 + (k + 9) * HW2);
            r1[p][4 * j]     = __ldg(pA1 + k * HW2);
            r1[p][4 * j + 1] = __ldg(pA1 + (k + 1) * HW2);
            r1[p][4 * j + 2] = __ldg(pA1 + (k + 8) * HW2);
            r1[p][4 * j + 3] = __ldg(pA1 + (k + 9) * HW2);
        }
    };

    auto issueB = [&](int ch) {
        const char* src = reinterpret_cast<const char*>(g_wimg + (size_t)ch * CHUNKW);
        const uint32_t dst = sbase + (uint32_t)((ch & 1) * CHUNK_BYTES);
        for (int u = tid; u < CP_UNITS; u += 128)
            cp_async16(dst + u * 16, src + u * 16);
        asm volatile("cp.async.commit_group;" ::: "memory");
    };

    ldgA(0, 0);
    ldgA(1, 1);
    issueB(0);

    for (int ch = 0; ch < NCH; ch++) {
        if (ch + 1 < NCH) {
            issueB(ch + 1);
            asm volatile("cp.async.wait_group 1;" ::: "memory");
        } else {
            asm volatile("cp.async.wait_group 0;" ::: "memory");
        }
        __syncthreads();

        const uint32_t* buf = smem + (ch & 1) * CHUNKW;

#pragma unroll
        for (int kk = 0; kk < 4; kk++) {
            const int sg = ch * 4 + kk;
            const int p  = sg & 1;

            uint32_t af[2][4];
#pragma unroll
            for (int j = 0; j < 2; j++) {
                af[j][0] = h2pack(r0[p][4 * j],     r0[p][4 * j + 1]);
                af[j][1] = h2pack(r1[p][4 * j],     r1[p][4 * j + 1]);
                af[j][2] = h2pack(r0[p][4 * j + 2], r0[p][4 * j + 3]);
                af[j][3] = h2pack(r1[p][4 * j + 2], r1[p][4 * j + 3]);
            }

            if (sg + 2 < NSTEP) ldgA(sg + 2, p);

#pragma unroll
            for (int j = 0; j < 2; j++) {
                const int s = kk * 2 + j;
#pragma unroll
                for (int tt = 0; tt < 3; tt++) {
                    const int t = nh * 3 + tt;
                    const uint2 bw = *reinterpret_cast<const uint2*>(
                        buf + (t * 8 + g) * ROWW + s * 8 + 2 * c);
                    hmma16816(acc[tt], af[j], bw.x, bw.y);
                }
            }
        }
        __syncthreads();
    }

    // ------------------- fused WSL epilogue -------------------
    float* xs = reinterpret_cast<float*>(smem);   // [32][XST], 6.3 KB

#pragma unroll
    for (int tt = 0; tt < 3; tt++) {
        const int n0 = (nh * 3 + tt) * 8 + 2 * c;
        const float bv0 = (n0 < 32) ? __ldg(down_b + n0) : 0.f;
        const float bv1 = (n0 + 1 < 32) ? __ldg(down_b + n0 + 1) : 0.f;
        xs[(mw + g) * XST + n0]         = acc[tt][0] + bv0;
        xs[(mw + g) * XST + n0 + 1]     = acc[tt][1] + bv1;
        xs[(mw + g + 8) * XST + n0]     = acc[tt][2] + bv0;
        xs[(mw + g + 8) * XST + n0 + 1] = acc[tt][3] + bv1;
    }
    __syncthreads();

    const int b_cta   = m_base / HW2;
    const int bsplit  = min(32, (b_cta + 1) * HW2 - m_base);  // rows < bsplit -> b_cta

    if (tid < 32) {
        // GMP: map = tid, per-b max then atomicMax
        const int map = tid;
        float mx0 = -INFINITY, mx1 = -INFINITY;
#pragma unroll 8
        for (int r = 0; r < 32; r++) {
            float v = xs[r * XST + map];
            if (r < bsplit) mx0 = fmaxf(mx0, v); else mx1 = fmaxf(mx1, v);
        }
        atomicMax(&g_gmp_u[b_cta * 32 + map], fenc(mx0));
        if (bsplit < 32)
            atomicMax(&g_gmp_u[(b_cta + 1) * 32 + map], fenc(mx1));
    } else if (tid < 64) {
        // csum (class sums) + t2 rows, direct stores in [m][8] layout
        const int r = tid - 32;
        const int m = m_base + r;
        float cs[8], t2v[8];
#pragma unroll
        for (int j = 0; j < 8; j++) {
            cs[j] = xs[r * XST + 4 * j] + xs[r * XST + 4 * j + 1] +
                    xs[r * XST + 4 * j + 2] + xs[r * XST + 4 * j + 3];
            t2v[j] = xs[r * XST + 40 + j];
        }
        float4* cd = reinterpret_cast<float4*>(g_csum + (size_t)m * 8);
        cd[0] = make_float4(cs[0], cs[1], cs[2], cs[3]);
        cd[1] = make_float4(cs[4], cs[5], cs[6], cs[7]);
        float4* td = reinterpret_cast<float4*>(g_t2 + (size_t)m * 8);
        td[0] = make_float4(t2v[0], t2v[1], t2v[2], t2v[3]);
        td[1] = make_float4(t2v[4], t2v[5], t2v[6], t2v[7]);
    } else {
        // t1 row sums (maps 32..39) -> atomicAdd partials
        const int idx  = tid - 64;
        const int j    = idx & 7;
        const int part = idx >> 3;        // 8 parts x 4 rows
        float sa = 0.f, sb = 0.f;
#pragma unroll
        for (int rr = 0; rr < 4; rr++) {
            const int r = part * 4 + rr;
            float v = xs[r * XST + 32 + j];
            if (r < bsplit) sa += v; else sb += v;
        }
        if (part * 4 < bsplit)
            atomicAdd(&g_t1s[b_cta * 8 + j], sa);
        if (part * 4 + 3 >= bsplit)
            atomicAdd(&g_t1s[(b_cta + 1) * 8 + j], sb);
    }
}

// ---------------------------------------------------------------------------
// Kernel B2: tiny finisher. Grid 64, 256 threads. Reads 0.8 MB.
// ---------------------------------------------------------------------------
__global__ void __launch_bounds__(256) wsl_b2_kernel(
    const float* __restrict__ fc_b,
    float* __restrict__ out,
    int B)
{
    __shared__ float gm[32];
    __shared__ float xout[8];
    __shared__ float red[8 * 8];
    __shared__ float psum[8];

    const int b = blockIdx.x;
    const int tid = threadIdx.x;
    const int w = tid >> 5, lane = tid & 31;

    if (tid < 32) gm[tid] = fdec(g_gmp_u[b * 32 + tid]);
    __syncthreads();

    if (tid == 0) {
        float sc[8];
        float mx = -INFINITY;
        for (int j = 0; j < 8; j++) {
            sc[j] = 0.25f * (gm[4 * j] + gm[4 * j + 1] + gm[4 * j + 2] + gm[4 * j + 3]);
            mx = fmaxf(mx, sc[j]);
        }
        float se = 0.f;
        for (int j = 0; j < 8; j++) se += expf(sc[j] - mx);
        float lse = mx + logf(se);
        for (int j = 0; j < 8; j++) {
            float v = sc[j] - lse;
            xout[j] = v;
            out[(size_t)b * 8 + j] = v;
        }
    }
    __syncthreads();

    float v[8];
    if (tid < HW2) {
        const size_t m = (size_t)b * HW2 + tid;
        const float4* cp = reinterpret_cast<const float4*>(g_csum + m * 8);
        float4 c0 = __ldg(cp), c1 = __ldg(cp + 1);
        float sal = xout[0] * c0.x + xout[1] * c0.y + xout[2] * c0.z + xout[3] * c0.w +
                    xout[4] * c1.x + xout[5] * c1.y + xout[6] * c1.z + xout[7] * c1.w;
        sal *= (1.f / 32.f);
        const float4* tp = reinterpret_cast<const float4*>(g_t2 + m * 8);
        float4 t0 = __ldg(tp), t1 = __ldg(tp + 1);
        v[0] = sal * t0.x; v[1] = sal * t0.y; v[2] = sal * t0.z; v[3] = sal * t0.w;
        v[4] = sal * t1.x; v[5] = sal * t1.y; v[6] = sal * t1.z; v[7] = sal * t1.w;
    } else {
#pragma unroll
        for (int j = 0; j < 8; j++) v[j] = 0.f;
    }
#pragma unroll
    for (int off = 16; off > 0; off >>= 1) {
#pragma unroll
        for (int j = 0; j < 8; j++)
            v[j] += __shfl_down_sync(0xffffffffu, v[j], off);
    }
    if (lane == 0) {
#pragma unroll
        for (int j = 0; j < 8; j++) red[j * 8 + w] = v[j];
    }
    __syncthreads();
    if (tid < 8) {
        float s = 0.f;
#pragma unroll
        for (int ww = 0; ww < 8; ww++) s += red[tid * 8 + ww];
        psum[tid] = s;
    }
    __syncthreads();

    if (tid == 0) {
        float lg[8];
        float mx = -INFINITY;
        for (int j = 0; j < 8; j++) {
            lg[j] = (g_t1s[b * 8 + j] + psum[j]) * (1.f / 196.f) + fc_b[j];
            mx = fmaxf(mx, lg[j]);
        }
        float se = 0.f;
        for (int j = 0; j < 8; j++) se += expf(lg[j] - mx);
        float lse = mx + logf(se);
        for (int j = 0; j < 8; j++)
            out[(size_t)B * 8 + (size_t)b * 8 + j] = lg[j] - lse;
    }
}

// ---------------------------------------------------------------------------
extern "C" void kernel_launch(void* const* d_in, const int* in_sizes, int n_in,
                              void* d_out, int out_size)
{
    const float* x      = (const float*)d_in[0];
    const float* down_w = (const float*)d_in[1];
    const float* down_b = (const float*)d_in[2];
    const float* fc_w   = (const float*)d_in[3];
    const float* fc_b   = (const float*)d_in[4];
    float* out = (float*)d_out;

    int B = in_sizes[0] / (C_TOT * HW2);   // 64

    wsl_prep_kernel<<<48, 256>>>(down_w, fc_w);
    wsl_mma_kernel<<<MTILES, 128>>>(x, down_b);
    wsl_b2_kernel<<<B, 256>>>(fc_b, out, B);
}

// round 9
// speedup vs baseline: 1.1182x; 1.1182x over previous
#include <cuda_runtime.h>
#include <cuda_fp16.h>
#include <cstdint>
#include <math.h>

// ---------------------------------------------------------------------------
// Problem constants
// ---------------------------------------------------------------------------
#define C_TOT   2048
#define HW2     196
#define O_REAL  48
#define MAXB    64
#define M_TILE  64
#define MTILES  196            // 12544 / 64
#define KSPLIT  2
#define K_PER   (C_TOT / KSPLIT)   // 1024
#define KC      128
#define NCH_CTA (K_PER / KC)   // 8 chunks per CTA
#define NCH_ALL (C_TOT / KC)   // 16 chunks total
#define NSTEP   (K_PER / 32)   // 32 k32 steps per CTA

// W fp16 image: per chunk, 48 rows x 68 words (64 data + 4 pad)
#define ROWW    68
#define CHUNKW  (48 * ROWW)            // 3264 words
#define CHUNK_BYTES (CHUNKW * 4)       // 13056
#define CP_UNITS (CHUNK_BYTES / 16)    // 816

#define XST     52                     // epilogue smem row stride (words)

// Scratch
__device__ uint32_t g_wimg[(size_t)NCH_ALL * CHUNKW];        // 209 KB
__device__ float    g_part[(size_t)KSPLIT * MTILES * M_TILE * O_REAL]; // 4.8 MB
__device__ int      g_tick[MTILES];
__device__ float    g_csum[(size_t)MAXB * HW2 * 8];          // [m][8]
__device__ float    g_t2[(size_t)MAXB * HW2 * 8];            // [m][8]
__device__ float    g_t1s[(size_t)MAXB * 8];                 // atomicAdd acc
__device__ unsigned g_gmp_u[(size_t)MAXB * 32];              // atomicMax acc

// ---------------------------------------------------------------------------
// helpers
// ---------------------------------------------------------------------------
__device__ __forceinline__ void hmma16816(float* c, const uint32_t* a,
                                          uint32_t b0, uint32_t b1) {
    asm volatile(
        "mma.sync.aligned.m16n8k16.row.col.f32.f16.f16.f32 "
        "{%0,%1,%2,%3}, {%4,%5,%6,%7}, {%8,%9}, {%0,%1,%2,%3};"
        : "+f"(c[0]), "+f"(c[1]), "+f"(c[2]), "+f"(c[3])
        : "r"(a[0]), "r"(a[1]), "r"(a[2]), "r"(a[3]), "r"(b0), "r"(b1));
}
__device__ __forceinline__ uint32_t h2pack(float e, float o) {
    uint32_t r;
    asm("cvt.rn.f16x2.f32 %0, %1, %2;" : "=r"(r) : "f"(o), "f"(e));
    return r;
}
__device__ __forceinline__ void cp_async16(uint32_t saddr, const void* gaddr) {
    asm volatile("cp.async.cg.shared.global [%0], [%1], 16;" :: "r"(saddr), "l"(gaddr));
}
__device__ __forceinline__ uint32_t smem_u32addr(const void* p) {
    uint32_t a;
    asm("{ .reg .u64 t; cvta.to.shared.u64 t, %1; cvt.u32.u64 %0, t; }" : "=r"(a) : "l"(p));
    return a;
}
// order-preserving float<->uint for atomicMax
__device__ __forceinline__ unsigned fenc(float f) {
    unsigned u = __float_as_uint(f);
    return (u & 0x80000000u) ? ~u : (u | 0x80000000u);
}
__device__ __forceinline__ float fdec(unsigned u) {
    return __uint_as_float((u & 0x80000000u) ? (u & 0x7FFFFFFFu) : ~u);
}

// ---------------------------------------------------------------------------
// Prep: W -> fp16 image (4 words/thread) + zero accumulators & tickets.
// ---------------------------------------------------------------------------
__global__ void __launch_bounds__(256) wsl_prep_kernel(
    const float* __restrict__ down_w,
    const float* __restrict__ fc_w)
{
    int q = blockIdx.x * 256 + threadIdx.x;

    if (q < MAXB * 32) g_gmp_u[q] = 0u;
    if (q < MAXB * 8)  g_t1s[q] = 0.f;
    if (q < MTILES)    g_tick[q] = 0;

    if (q >= NCH_ALL * 48 * 16) return;
    int ci  = q / 768;
    int rem = q - ci * 768;
    int n   = rem >> 4;
    int qd  = rem & 15;
    int s   = qd >> 1;
    int bk  = s * 16 + 4 * (qd & 1);

    const float* wr;
    if (n < 32)      wr = down_w + (size_t)n * C_TOT;
    else if (n < 40) wr = fc_w + (size_t)(n - 32) * (2 * C_TOT);
    else             wr = fc_w + (size_t)(n - 40) * (2 * C_TOT) + C_TOT;

    const float* src = wr + ci * KC + bk;
    float4 f0 = *reinterpret_cast<const float4*>(src);
    float4 f1 = *reinterpret_cast<const float4*>(src + 8);

    uint4 v;
    v.x = h2pack(f0.x, f0.y);
    v.y = h2pack(f1.x, f1.y);
    v.z = h2pack(f0.z, f0.w);
    v.w = h2pack(f1.z, f1.w);
    *reinterpret_cast<uint4*>(g_wimg + (size_t)ci * CHUNKW + n * ROWW + qd * 4) = v;
}

// ---------------------------------------------------------------------------
// Kernel A: fp16 GEMM (R7 config) + split-K ticket + fused WSL epilogue.
// Grid (196, 2), 128 threads. Warp w: m rows [w*16, w*16+16), all 48 n.
// ---------------------------------------------------------------------------
__global__ void __launch_bounds__(128) wsl_mma_kernel(
    const float* __restrict__ x,
    const float* __restrict__ down_b)
{
    __shared__ __align__(16) uint32_t smem[2 * CHUNKW];   // 26.1 KB
    __shared__ int s_islast;
    const uint32_t sbase = smem_u32addr(smem);

    const int tid  = threadIdx.x;
    const int wid  = tid >> 5;
    const int lane = tid & 31;
    const int g    = lane >> 2;
    const int c    = lane & 3;
    const int mw   = wid * 16;
    const int tile = blockIdx.x;
    const int ks   = blockIdx.y;
    const int m_base  = tile * M_TILE;
    const int ks_base = ks * K_PER;
    const int ch0     = ks * NCH_CTA;

    const int m0 = m_base + mw + g;
    const int m1 = m0 + 8;
    const int b0r = m0 / HW2, hw0 = m0 - b0r * HW2;
    const int b1r = m1 / HW2, hw1 = m1 - b1r * HW2;
    const float* pA0 = x + ((size_t)b0r * C_TOT) * HW2 + hw0;
    const float* pA1 = x + ((size_t)b1r * C_TOT) * HW2 + hw1;

    float acc[6][4];
#pragma unroll
    for (int t = 0; t < 6; t++)
#pragma unroll
        for (int j = 0; j < 4; j++) acc[t][j] = 0.f;

    float r0[2][8], r1[2][8];

    auto ldgA = [&](int sg, int p) {
        const int kb = ks_base + sg * 32 + 2 * c;
#pragma unroll
        for (int j = 0; j < 2; j++) {
            const size_t k = (size_t)(kb + 16 * j);
            r0[p][4 * j]     = __ldg(pA0 + k * HW2);
            r0[p][4 * j + 1] = __ldg(pA0 + (k + 1) * HW2);
            r0[p][4 * j + 2] = __ldg(pA0 + (k + 8) * HW2);
            r0[p][4 * j + 3] = __ldg(pA0 + (k + 9) * HW2);
            r1[p][4 * j]     = __ldg(pA1 + k * HW2);
            r1[p][4 * j + 1] = __ldg(pA1 + (k + 1) * HW2);
            r1[p][4 * j + 2] = __ldg(pA1 + (k + 8) * HW2);
            r1[p][4 * j + 3] = __ldg(pA1 + (k + 9) * HW2);
        }
    };

    auto issueB = [&](int ch) {
        const char* src = reinterpret_cast<const char*>(g_wimg + (size_t)(ch0 + ch) * CHUNKW);
        const uint32_t dst = sbase + (uint32_t)((ch & 1) * CHUNK_BYTES);
        for (int u = tid; u < CP_UNITS; u += 128)
            cp_async16(dst + u * 16, src + u * 16);
        asm volatile("cp.async.commit_group;" ::: "memory");
    };

    ldgA(0, 0);
    ldgA(1, 1);
    issueB(0);

    for (int ch = 0; ch < NCH_CTA; ch++) {
        if (ch + 1 < NCH_CTA) {
            issueB(ch + 1);
            asm volatile("cp.async.wait_group 1;" ::: "memory");
        } else {
            asm volatile("cp.async.wait_group 0;" ::: "memory");
        }
        __syncthreads();

        const uint32_t* buf = smem + (ch & 1) * CHUNKW;

#pragma unroll
        for (int kk = 0; kk < 4; kk++) {
            const int sg = ch * 4 + kk;
            const int p  = sg & 1;

            uint32_t af[2][4];
#pragma unroll
            for (int j = 0; j < 2; j++) {
                af[j][0] = h2pack(r0[p][4 * j],     r0[p][4 * j + 1]);
                af[j][1] = h2pack(r1[p][4 * j],     r1[p][4 * j + 1]);
                af[j][2] = h2pack(r0[p][4 * j + 2], r0[p][4 * j + 3]);
                af[j][3] = h2pack(r1[p][4 * j + 2], r1[p][4 * j + 3]);
            }

            if (sg + 2 < NSTEP) ldgA(sg + 2, p);

#pragma unroll
            for (int j = 0; j < 2; j++) {
                const int s = kk * 2 + j;
#pragma unroll
                for (int t = 0; t < 6; t++) {
                    const uint2 bw = *reinterpret_cast<const uint2*>(
                        buf + (t * 8 + g) * ROWW + s * 8 + 2 * c);
                    hmma16816(acc[t], af[j], bw.x, bw.y);
                }
            }
        }
        __syncthreads();
    }

    // ---- stash acc into smem xs[64][XST] ----
    float* xs = reinterpret_cast<float*>(smem);   // 64*52*4 = 13.3 KB
#pragma unroll
    for (int t = 0; t < 6; t++) {
        const int n0 = t * 8 + 2 * c;
        xs[(mw + g) * XST + n0]         = acc[t][0];
        xs[(mw + g) * XST + n0 + 1]     = acc[t][1];
        xs[(mw + g + 8) * XST + n0]     = acc[t][2];
        xs[(mw + g + 8) * XST + n0 + 1] = acc[t][3];
    }
    __syncthreads();

    // ---- write coalesced partial image [ks][tile][64][48] ----
    {
        float4* dst = reinterpret_cast<float4*>(
            g_part + ((size_t)ks * MTILES + tile) * (M_TILE * O_REAL));
#pragma unroll
        for (int i = 0; i < 6; i++) {
            const int fi = tid + i * 128;           // 768 float4s
            const int r = (fi * 4) / O_REAL;
            const int cc = (fi * 4) % O_REAL;
            dst[fi] = *reinterpret_cast<const float4*>(xs + r * XST + cc);
        }
    }

    // ---- split-K ticket ----
    __threadfence();
    __syncthreads();
    if (tid == 0) s_islast = (atomicAdd(&g_tick[tile], 1) == 1);
    __syncthreads();
    if (!s_islast) return;
    __threadfence();

    // ---- finisher: combine both partials (+bias) into xs ----
    {
        const float4* p0 = reinterpret_cast<const float4*>(
            g_part + (size_t)tile * (M_TILE * O_REAL));
        const float4* p1 = reinterpret_cast<const float4*>(
            g_part + ((size_t)MTILES + tile) * (M_TILE * O_REAL));
#pragma unroll
        for (int i = 0; i < 6; i++) {
            const int fi = tid + i * 128;
            const int r = (fi * 4) / O_REAL;
            const int cc = (fi * 4) % O_REAL;
            float4 a = p0[fi];
            float4 b = p1[fi];
            float4 v = make_float4(a.x + b.x, a.y + b.y, a.z + b.z, a.w + b.w);
            if (cc < 32) {   // 4-aligned, 32 % 4 == 0 -> whole vec biased or none
                v.x += __ldg(down_b + cc);
                v.y += __ldg(down_b + cc + 1);
                v.z += __ldg(down_b + cc + 2);
                v.w += __ldg(down_b + cc + 3);
            }
            *reinterpret_cast<float4*>(xs + r * XST + cc) = v;
        }
    }
    __syncthreads();

    // ---- fused WSL epilogue (verified mechanism from R8) ----
    const int b_cta  = m_base / HW2;
    const int bsplit = min(M_TILE, (b_cta + 1) * HW2 - m_base);

    if (tid < 32) {
        const int map = tid;
        float mx0 = -INFINITY, mx1 = -INFINITY;
#pragma unroll 8
        for (int r = 0; r < M_TILE; r++) {
            float v = xs[r * XST + map];
            if (r < bsplit) mx0 = fmaxf(mx0, v); else mx1 = fmaxf(mx1, v);
        }
        atomicMax(&g_gmp_u[b_cta * 32 + map], fenc(mx0));
        if (bsplit < M_TILE)
            atomicMax(&g_gmp_u[(b_cta + 1) * 32 + map], fenc(mx1));
    } else if (tid < 96) {
        const int r = tid - 32;
        const int m = m_base + r;
        float cs[8], t2v[8];
#pragma unroll
        for (int j = 0; j < 8; j++) {
            cs[j] = xs[r * XST + 4 * j] + xs[r * XST + 4 * j + 1] +
                    xs[r * XST + 4 * j + 2] + xs[r * XST + 4 * j + 3];
            t2v[j] = xs[r * XST + 40 + j];
        }
        float4* cd = reinterpret_cast<float4*>(g_csum + (size_t)m * 8);
        cd[0] = make_float4(cs[0], cs[1], cs[2], cs[3]);
        cd[1] = make_float4(cs[4], cs[5], cs[6], cs[7]);
        float4* td = reinterpret_cast<float4*>(g_t2 + (size_t)m * 8);
        td[0] = make_float4(t2v[0], t2v[1], t2v[2], t2v[3]);
        td[1] = make_float4(t2v[4], t2v[5], t2v[6], t2v[7]);
    } else {
        const int idx  = tid - 96;       // 32 threads: 8 j x 4 parts
        const int j    = idx & 7;
        const int part = idx >> 3;       // 4 parts x 16 rows
        float sa = 0.f, sb = 0.f;
#pragma unroll
        for (int rr = 0; rr < 16; rr++) {
            const int r = part * 16 + rr;
            float v = xs[r * XST + 32 + j];
            if (r < bsplit) sa += v; else sb += v;
        }
        if (part * 16 < bsplit)
            atomicAdd(&g_t1s[b_cta * 8 + j], sa);
        if (part * 16 + 15 >= bsplit)
            atomicAdd(&g_t1s[(b_cta + 1) * 8 + j], sb);
    }
}

// ---------------------------------------------------------------------------
// Kernel B2: tiny finisher. Grid 64, 256 threads. Reads 0.8 MB.
// ---------------------------------------------------------------------------
__global__ void __launch_bounds__(256) wsl_b2_kernel(
    const float* __restrict__ fc_b,
    float* __restrict__ out,
    int B)
{
    __shared__ float gm[32];
    __shared__ float xout[8];
    __shared__ float red[8 * 8];
    __shared__ float psum[8];

    const int b = blockIdx.x;
    const int tid = threadIdx.x;
    const int w = tid >> 5, lane = tid & 31;

    if (tid < 32) gm[tid] = fdec(g_gmp_u[b * 32 + tid]);
    __syncthreads();

    if (tid == 0) {
        float sc[8];
        float mx = -INFINITY;
        for (int j = 0; j < 8; j++) {
            sc[j] = 0.25f * (gm[4 * j] + gm[4 * j + 1] + gm[4 * j + 2] + gm[4 * j + 3]);
            mx = fmaxf(mx, sc[j]);
        }
        float se = 0.f;
        for (int j = 0; j < 8; j++) se += expf(sc[j] - mx);
        float lse = mx + logf(se);
        for (int j = 0; j < 8; j++) {
            float v = sc[j] - lse;
            xout[j] = v;
            out[(size_t)b * 8 + j] = v;
        }
    }
    __syncthreads();

    float v[8];
    if (tid < HW2) {
        const size_t m = (size_t)b * HW2 + tid;
        const float4* cp = reinterpret_cast<const float4*>(g_csum + m * 8);
        float4 c0 = __ldg(cp), c1 = __ldg(cp + 1);
        float sal = xout[0] * c0.x + xout[1] * c0.y + xout[2] * c0.z + xout[3] * c0.w +
                    xout[4] * c1.x + xout[5] * c1.y + xout[6] * c1.z + xout[7] * c1.w;
        sal *= (1.f / 32.f);
        const float4* tp = reinterpret_cast<const float4*>(g_t2 + m * 8);
        float4 t0 = __ldg(tp), t1 = __ldg(tp + 1);
        v[0] = sal * t0.x; v[1] = sal * t0.y; v[2] = sal * t0.z; v[3] = sal * t0.w;
        v[4] = sal * t1.x; v[5] = sal * t1.y; v[6] = sal * t1.z; v[7] = sal * t1.w;
    } else {
#pragma unroll
        for (int j = 0; j < 8; j++) v[j] = 0.f;
    }
#pragma unroll
    for (int off = 16; off > 0; off >>= 1) {
#pragma unroll
        for (int j = 0; j < 8; j++)
            v[j] += __shfl_down_sync(0xffffffffu, v[j], off);
    }
    if (lane == 0) {
#pragma unroll
        for (int j = 0; j < 8; j++) red[j * 8 + w] = v[j];
    }
    __syncthreads();
    if (tid < 8) {
        float s = 0.f;
#pragma unroll
        for (int ww = 0; ww < 8; ww++) s += red[tid * 8 + ww];
        psum[tid] = s;
    }
    __syncthreads();

    if (tid == 0) {
        float lg[8];
        float mx = -INFINITY;
        for (int j = 0; j < 8; j++) {
            lg[j] = (g_t1s[b * 8 + j] + psum[j]) * (1.f / 196.f) + fc_b[j];
            mx = fmaxf(mx, lg[j]);
        }
        float se = 0.f;
        for (int j = 0; j < 8; j++) se += expf(lg[j] - mx);
        float lse = mx + logf(se);
        for (int j = 0; j < 8; j++)
            out[(size_t)B * 8 + (size_t)b * 8 + j] = lg[j] - lse;
    }
}

// ---------------------------------------------------------------------------
extern "C" void kernel_launch(void* const* d_in, const int* in_sizes, int n_in,
                              void* d_out, int out_size)
{
    const float* x      = (const float*)d_in[0];
    const float* down_w = (const float*)d_in[1];
    const float* down_b = (const float*)d_in[2];
    const float* fc_w   = (const float*)d_in[3];
    const float* fc_b   = (const float*)d_in[4];
    float* out = (float*)d_out;

    int B = in_sizes[0] / (C_TOT * HW2);   // 64

    wsl_prep_kernel<<<48, 256>>>(down_w, fc_w);
    dim3 gridA(MTILES, KSPLIT);
    wsl_mma_kernel<<<gridA, 128>>>(x, down_b);
    wsl_b2_kernel<<<B, 256>>>(fc_b, out, B);
}

// round 10
// speedup vs baseline: 1.1665x; 1.0432x over previous
#include <cuda_runtime.h>
#include <cuda_fp16.h>
#include <cstdint>
#include <math.h>

// ---------------------------------------------------------------------------
// Problem constants
// ---------------------------------------------------------------------------
#define C_TOT   2048
#define HW2     196
#define O_REAL  48
#define MAXB    64
#define M_TILE  64
#define MTILES  196            // 12544 / 64
#define KSPLIT  2
#define K_PER   (C_TOT / KSPLIT)   // 1024
#define KC      128
#define NCH_CTA (K_PER / KC)   // 8 chunks per CTA
#define NCH_ALL (C_TOT / KC)   // 16 chunks total
#define NSTEP   (K_PER / 32)   // 32 k32 steps per CTA

// W fp16 image: per chunk, 48 rows x 68 words (64 data + 4 pad)
#define ROWW    68
#define CHUNKW  (48 * ROWW)            // 3264 words
#define CHUNK_BYTES (CHUNKW * 4)       // 13056
#define CP_UNITS (CHUNK_BYTES / 16)    // 816

#define XST     52                     // epilogue smem row stride (words)

// Scratch
__device__ uint32_t g_wimg[(size_t)NCH_ALL * CHUNKW];                   // 209 KB
__device__ float    g_part[(size_t)KSPLIT * MTILES * M_TILE * O_REAL]; // 4.8 MB
__device__ float    g_csum[(size_t)MAXB * HW2 * 8];          // [m][8]
__device__ float    g_t2[(size_t)MAXB * HW2 * 8];            // [m][8]
__device__ float    g_t1s[(size_t)MAXB * 8];                 // atomicAdd acc
__device__ unsigned g_gmp_u[(size_t)MAXB * 32];              // atomicMax acc

// ---------------------------------------------------------------------------
// helpers
// ---------------------------------------------------------------------------
__device__ __forceinline__ void hmma16816(float* c, const uint32_t* a,
                                          uint32_t b0, uint32_t b1) {
    asm volatile(
        "mma.sync.aligned.m16n8k16.row.col.f32.f16.f16.f32 "
        "{%0,%1,%2,%3}, {%4,%5,%6,%7}, {%8,%9}, {%0,%1,%2,%3};"
        : "+f"(c[0]), "+f"(c[1]), "+f"(c[2]), "+f"(c[3])
        : "r"(a[0]), "r"(a[1]), "r"(a[2]), "r"(a[3]), "r"(b0), "r"(b1));
}
__device__ __forceinline__ uint32_t h2pack(float e, float o) {
    uint32_t r;
    asm("cvt.rn.f16x2.f32 %0, %1, %2;" : "=r"(r) : "f"(o), "f"(e));
    return r;
}
__device__ __forceinline__ void cp_async16(uint32_t saddr, const void* gaddr) {
    asm volatile("cp.async.cg.shared.global [%0], [%1], 16;" :: "r"(saddr), "l"(gaddr));
}
__device__ __forceinline__ uint32_t smem_u32addr(const void* p) {
    uint32_t a;
    asm("{ .reg .u64 t; cvta.to.shared.u64 t, %1; cvt.u32.u64 %0, t; }" : "=r"(a) : "l"(p));
    return a;
}
// order-preserving float<->uint for atomicMax
__device__ __forceinline__ unsigned fenc(float f) {
    unsigned u = __float_as_uint(f);
    return (u & 0x80000000u) ? ~u : (u | 0x80000000u);
}
__device__ __forceinline__ float fdec(unsigned u) {
    return __uint_as_float((u & 0x80000000u) ? (u & 0x7FFFFFFFu) : ~u);
}

// ---------------------------------------------------------------------------
// Prep: W -> fp16 image (4 words/thread) + zero accumulators.
// ---------------------------------------------------------------------------
__global__ void __launch_bounds__(256) wsl_prep_kernel(
    const float* __restrict__ down_w,
    const float* __restrict__ fc_w)
{
    int q = blockIdx.x * 256 + threadIdx.x;

    if (q < MAXB * 32) g_gmp_u[q] = 0u;
    if (q < MAXB * 8)  g_t1s[q] = 0.f;

    if (q >= NCH_ALL * 48 * 16) return;
    int ci  = q / 768;
    int rem = q - ci * 768;
    int n   = rem >> 4;
    int qd  = rem & 15;
    int s   = qd >> 1;
    int bk  = s * 16 + 4 * (qd & 1);

    const float* wr;
    if (n < 32)      wr = down_w + (size_t)n * C_TOT;
    else if (n < 40) wr = fc_w + (size_t)(n - 32) * (2 * C_TOT);
    else             wr = fc_w + (size_t)(n - 40) * (2 * C_TOT) + C_TOT;

    const float* src = wr + ci * KC + bk;
    float4 f0 = *reinterpret_cast<const float4*>(src);
    float4 f1 = *reinterpret_cast<const float4*>(src + 8);

    uint4 v;
    v.x = h2pack(f0.x, f0.y);
    v.y = h2pack(f1.x, f1.y);
    v.z = h2pack(f0.z, f0.w);
    v.w = h2pack(f1.z, f1.w);
    *reinterpret_cast<uint4*>(g_wimg + (size_t)ci * CHUNKW + n * ROWW + qd * 4) = v;
}

// ---------------------------------------------------------------------------
// Kernel A: fp16 GEMM (R7 config), coalesced partial write.
// Grid (196, 2), 128 threads. Warp w: m rows [w*16, w*16+16), all 48 n.
// ---------------------------------------------------------------------------
__global__ void __launch_bounds__(128) wsl_mma_kernel(const float* __restrict__ x)
{
    __shared__ __align__(16) uint32_t smem[2 * CHUNKW];   // 26.1 KB
    const uint32_t sbase = smem_u32addr(smem);

    const int tid  = threadIdx.x;
    const int wid  = tid >> 5;
    const int lane = tid & 31;
    const int g    = lane >> 2;
    const int c    = lane & 3;
    const int mw   = wid * 16;
    const int tile = blockIdx.x;
    const int ks   = blockIdx.y;
    const int m_base  = tile * M_TILE;
    const int ks_base = ks * K_PER;
    const int ch0     = ks * NCH_CTA;

    const int m0 = m_base + mw + g;
    const int m1 = m0 + 8;
    const int b0r = m0 / HW2, hw0 = m0 - b0r * HW2;
    const int b1r = m1 / HW2, hw1 = m1 - b1r * HW2;
    const float* pA0 = x + ((size_t)b0r * C_TOT) * HW2 + hw0;
    const float* pA1 = x + ((size_t)b1r * C_TOT) * HW2 + hw1;

    float acc[6][4];
#pragma unroll
    for (int t = 0; t < 6; t++)
#pragma unroll
        for (int j = 0; j < 4; j++) acc[t][j] = 0.f;

    float r0[2][8], r1[2][8];

    auto ldgA = [&](int sg, int p) {
        const int kb = ks_base + sg * 32 + 2 * c;
#pragma unroll
        for (int j = 0; j < 2; j++) {
            const size_t k = (size_t)(kb + 16 * j);
            r0[p][4 * j]     = __ldg(pA0 + k * HW2);
            r0[p][4 * j + 1] = __ldg(pA0 + (k + 1) * HW2);
            r0[p][4 * j + 2] = __ldg(pA0 + (k + 8) * HW2);
            r0[p][4 * j + 3] = __ldg(pA0 + (k + 9) * HW2);
            r1[p][4 * j]     = __ldg(pA1 + k * HW2);
            r1[p][4 * j + 1] = __ldg(pA1 + (k + 1) * HW2);
            r1[p][4 * j + 2] = __ldg(pA1 + (k + 8) * HW2);
            r1[p][4 * j + 3] = __ldg(pA1 + (k + 9) * HW2);
        }
    };

    auto issueB = [&](int ch) {
        const char* src = reinterpret_cast<const char*>(g_wimg + (size_t)(ch0 + ch) * CHUNKW);
        const uint32_t dst = sbase + (uint32_t)((ch & 1) * CHUNK_BYTES);
        for (int u = tid; u < CP_UNITS; u += 128)
            cp_async16(dst + u * 16, src + u * 16);
        asm volatile("cp.async.commit_group;" ::: "memory");
    };

    ldgA(0, 0);
    ldgA(1, 1);
    issueB(0);

    for (int ch = 0; ch < NCH_CTA; ch++) {
        if (ch + 1 < NCH_CTA) {
            issueB(ch + 1);
            asm volatile("cp.async.wait_group 1;" ::: "memory");
        } else {
            asm volatile("cp.async.wait_group 0;" ::: "memory");
        }
        __syncthreads();

        const uint32_t* buf = smem + (ch & 1) * CHUNKW;

#pragma unroll
        for (int kk = 0; kk < 4; kk++) {
            const int sg = ch * 4 + kk;
            const int p  = sg & 1;

            uint32_t af[2][4];
#pragma unroll
            for (int j = 0; j < 2; j++) {
                af[j][0] = h2pack(r0[p][4 * j],     r0[p][4 * j + 1]);
                af[j][1] = h2pack(r1[p][4 * j],     r1[p][4 * j + 1]);
                af[j][2] = h2pack(r0[p][4 * j + 2], r0[p][4 * j + 3]);
                af[j][3] = h2pack(r1[p][4 * j + 2], r1[p][4 * j + 3]);
            }

            if (sg + 2 < NSTEP) ldgA(sg + 2, p);

#pragma unroll
            for (int j = 0; j < 2; j++) {
                const int s = kk * 2 + j;
#pragma unroll
                for (int t = 0; t < 6; t++) {
                    const uint2 bw = *reinterpret_cast<const uint2*>(
                        buf + (t * 8 + g) * ROWW + s * 8 + 2 * c);
                    hmma16816(acc[t], af[j], bw.x, bw.y);
                }
            }
        }
        __syncthreads();
    }

    // ---- stash acc into smem xs[64][XST], then coalesced partial write ----
    float* xs = reinterpret_cast<float*>(smem);   // 13.3 KB
#pragma unroll
    for (int t = 0; t < 6; t++) {
        const int n0 = t * 8 + 2 * c;
        xs[(mw + g) * XST + n0]         = acc[t][0];
        xs[(mw + g) * XST + n0 + 1]     = acc[t][1];
        xs[(mw + g + 8) * XST + n0]     = acc[t][2];
        xs[(mw + g + 8) * XST + n0 + 1] = acc[t][3];
    }
    __syncthreads();

    {
        float4* dst = reinterpret_cast<float4*>(
            g_part + ((size_t)ks * MTILES + tile) * (M_TILE * O_REAL));
#pragma unroll
        for (int i = 0; i < 6; i++) {
            const int fi = tid + i * 128;           // 768 float4s
            const int r  = (fi * 4) / O_REAL;
            const int cc = (fi * 4) % O_REAL;
            dst[fi] = *reinterpret_cast<const float4*>(xs + r * XST + cc);
        }
    }
}

// ---------------------------------------------------------------------------
// Kernel B1: per-tile combine + fused WSL reductions. Grid 196, 128 thr.
// Partials are L2-hot (written by kernel A just before).
// ---------------------------------------------------------------------------
__global__ void __launch_bounds__(128) wsl_b1_kernel(const float* __restrict__ down_b)
{
    __shared__ __align__(16) float xs[M_TILE * XST];   // 13.3 KB

    const int tid  = threadIdx.x;
    const int tile = blockIdx.x;
    const int m_base = tile * M_TILE;

    // combine both K-split partials (+ bias)
    {
        const float4* p0 = reinterpret_cast<const float4*>(
            g_part + (size_t)tile * (M_TILE * O_REAL));
        const float4* p1 = reinterpret_cast<const float4*>(
            g_part + ((size_t)MTILES + tile) * (M_TILE * O_REAL));
#pragma unroll
        for (int i = 0; i < 6; i++) {
            const int fi = tid + i * 128;
            const int r  = (fi * 4) / O_REAL;
            const int cc = (fi * 4) % O_REAL;
            float4 a = __ldg(p0 + fi);
            float4 b = __ldg(p1 + fi);
            float4 v = make_float4(a.x + b.x, a.y + b.y, a.z + b.z, a.w + b.w);
            if (cc < 32) {
                v.x += __ldg(down_b + cc);
                v.y += __ldg(down_b + cc + 1);
                v.z += __ldg(down_b + cc + 2);
                v.w += __ldg(down_b + cc + 3);
            }
            *reinterpret_cast<float4*>(xs + r * XST + cc) = v;
        }
    }
    __syncthreads();

    const int b_cta  = m_base / HW2;
    const int bsplit = min(M_TILE, (b_cta + 1) * HW2 - m_base);

    if (tid < 32) {
        // GMP per map
        const int map = tid;
        float mx0 = -INFINITY, mx1 = -INFINITY;
#pragma unroll 8
        for (int r = 0; r < M_TILE; r++) {
            float v = xs[r * XST + map];
            if (r < bsplit) mx0 = fmaxf(mx0, v); else mx1 = fmaxf(mx1, v);
        }
        atomicMax(&g_gmp_u[b_cta * 32 + map], fenc(mx0));
        if (bsplit < M_TILE)
            atomicMax(&g_gmp_u[(b_cta + 1) * 32 + map], fenc(mx1));
    } else if (tid < 96) {
        // csum + t2 rows, [m][8] layout
        const int r = tid - 32;
        const int m = m_base + r;
        float cs[8], t2v[8];
#pragma unroll
        for (int j = 0; j < 8; j++) {
            cs[j] = xs[r * XST + 4 * j] + xs[r * XST + 4 * j + 1] +
                    xs[r * XST + 4 * j + 2] + xs[r * XST + 4 * j + 3];
            t2v[j] = xs[r * XST + 40 + j];
        }
        float4* cd = reinterpret_cast<float4*>(g_csum + (size_t)m * 8);
        cd[0] = make_float4(cs[0], cs[1], cs[2], cs[3]);
        cd[1] = make_float4(cs[4], cs[5], cs[6], cs[7]);
        float4* td = reinterpret_cast<float4*>(g_t2 + (size_t)m * 8);
        td[0] = make_float4(t2v[0], t2v[1], t2v[2], t2v[3]);
        td[1] = make_float4(t2v[4], t2v[5], t2v[6], t2v[7]);
    } else {
        // t1 row sums -> atomicAdd partials
        const int idx  = tid - 96;       // 8 j x 4 parts
        const int j    = idx & 7;
        const int part = idx >> 3;       // 4 parts x 16 rows
        float sa = 0.f, sb = 0.f;
#pragma unroll
        for (int rr = 0; rr < 16; rr++) {
            const int r = part * 16 + rr;
            float v = xs[r * XST + 32 + j];
            if (r < bsplit) sa += v; else sb += v;
        }
        if (part * 16 < bsplit)
            atomicAdd(&g_t1s[b_cta * 8 + j], sa);
        if (part * 16 + 15 >= bsplit)
            atomicAdd(&g_t1s[(b_cta + 1) * 8 + j], sb);
    }
}

// ---------------------------------------------------------------------------
// Kernel B2: tiny finisher. Grid 64, 256 threads. Reads 0.8 MB.
// ---------------------------------------------------------------------------
__global__ void __launch_bounds__(256) wsl_b2_kernel(
    const float* __restrict__ fc_b,
    float* __restrict__ out,
    int B)
{
    __shared__ float gm[32];
    __shared__ float xout[8];
    __shared__ float red[8 * 8];
    __shared__ float psum[8];

    const int b = blockIdx.x;
    const int tid = threadIdx.x;
    const int w = tid >> 5, lane = tid & 31;

    if (tid < 32) gm[tid] = fdec(g_gmp_u[b * 32 + tid]);
    __syncthreads();

    if (tid == 0) {
        float sc[8];
        float mx = -INFINITY;
        for (int j = 0; j < 8; j++) {
            sc[j] = 0.25f * (gm[4 * j] + gm[4 * j + 1] + gm[4 * j + 2] + gm[4 * j + 3]);
            mx = fmaxf(mx, sc[j]);
        }
        float se = 0.f;
        for (int j = 0; j < 8; j++) se += expf(sc[j] - mx);
        float lse = mx + logf(se);
        for (int j = 0; j < 8; j++) {
            float v = sc[j] - lse;
            xout[j] = v;
            out[(size_t)b * 8 + j] = v;
        }
    }
    __syncthreads();

    float v[8];
    if (tid < HW2) {
        const size_t m = (size_t)b * HW2 + tid;
        const float4* cp = reinterpret_cast<const float4*>(g_csum + m * 8);
        float4 c0 = __ldg(cp), c1 = __ldg(cp + 1);
        float sal = xout[0] * c0.x + xout[1] * c0.y + xout[2] * c0.z + xout[3] * c0.w +
                    xout[4] * c1.x + xout[5] * c1.y + xout[6] * c1.z + xout[7] * c1.w;
        sal *= (1.f / 32.f);
        const float4* tp = reinterpret_cast<const float4*>(g_t2 + m * 8);
        float4 t0 = __ldg(tp), t1 = __ldg(tp + 1);
        v[0] = sal * t0.x; v[1] = sal * t0.y; v[2] = sal * t0.z; v[3] = sal * t0.w;
        v[4] = sal * t1.x; v[5] = sal * t1.y; v[6] = sal * t1.z; v[7] = sal * t1.w;
    } else {
#pragma unroll
        for (int j = 0; j < 8; j++) v[j] = 0.f;
    }
#pragma unroll
    for (int off = 16; off > 0; off >>= 1) {
#pragma unroll
        for (int j = 0; j < 8; j++)
            v[j] += __shfl_down_sync(0xffffffffu, v[j], off);
    }
    if (lane == 0) {
#pragma unroll
        for (int j = 0; j < 8; j++) red[j * 8 + w] = v[j];
    }
    __syncthreads();
    if (tid < 8) {
        float s = 0.f;
#pragma unroll
        for (int ww = 0; ww < 8; ww++) s += red[tid * 8 + ww];
        psum[tid] = s;
    }
    __syncthreads();

    if (tid == 0) {
        float lg[8];
        float mx = -INFINITY;
        for (int j = 0; j < 8; j++) {
            lg[j] = (g_t1s[b * 8 + j] + psum[j]) * (1.f / 196.f) + fc_b[j];
            mx = fmaxf(mx, lg[j]);
        }
        float se = 0.f;
        for (int j = 0; j < 8; j++) se += expf(lg[j] - mx);
        float lse = mx + logf(se);
        for (int j = 0; j < 8; j++)
            out[(size_t)B * 8 + (size_t)b * 8 + j] = lg[j] - lse;
    }
}

// ---------------------------------------------------------------------------
extern "C" void kernel_launch(void* const* d_in, const int* in_sizes, int n_in,
                              void* d_out, int out_size)
{
    const float* x      = (const float*)d_in[0];
    const float* down_w = (const float*)d_in[1];
    const float* down_b = (const float*)d_in[2];
    const float* fc_w   = (const float*)d_in[3];
    const float* fc_b   = (const float*)d_in[4];
    float* out = (float*)d_out;

    int B = in_sizes[0] / (C_TOT * HW2);   // 64

    wsl_prep_kernel<<<48, 256>>>(down_w, fc_w);
    dim3 gridA(MTILES, KSPLIT);
    wsl_mma_kernel<<<gridA, 128>>>(x);
    wsl_b1_kernel<<<MTILES, 128>>>(down_b);
    wsl_b2_kernel<<<B, 256>>>(fc_b, out, B);
}